// round 17
// baseline (speedup 1.0000x reference)
#include <cuda_runtime.h>
#include <cuda_bf16.h>

// ---------------- problem constants ----------------
#define BB     2
#define LLEN   2048
#define DMODEL 1536
#define HH     12
#define FDIM   16
#define DVDIM  128
#define D2     256
#define CH     128
#define NC     16
#define NTOK   4096
#define QKDIM  192
#define LN_EPS 1e-5f
#define EPS    1e-12f
#define MKS    40                 // MK tile k-stride (bf16)
#define KNS    136                // KN tile n-stride (bf16)
#define ABYT   (128 * MKS * 2)    // 10240 B per MK buffer
#define BBYT   (32 * KNS * 2)     // 8704 B per KN buffer
#define GSTR   (2 * ABYT + 2 * BBYT)  // 37888: double-buffer stride
#define KSTR   (4 * BBYT)             // 34816: kvstate buffer stride
// attn_fused layout: [2*GSTR buffers][qsm 8704][dens 512][Areg 4*2*ABYT]
#define AQSM   (2 * GSTR)
#define ADEN   (2 * GSTR + 8704)
#define AREG   (2 * GSTR + 8704 + 512)
#define ATTN_SM (AREG + 8 * ABYT)     // 166912

typedef __nv_bfloat16 bf16;

// ---------------- scratch (device globals) ----------------
__device__ float g_q [NTOK * QKDIM];
__device__ float g_k [NTOK * QKDIM];
__device__ float g_v [(size_t)NTOK * DMODEL];
__device__ float g_S [(size_t)BB * HH * NC * D2 * DVDIM];
__device__ float g_z [(size_t)BB * HH * NC * D2];
__device__ float g_oh[(size_t)NTOK * DMODEL];

// ---------------- helpers ----------------
__device__ __forceinline__ unsigned sptr(const void* p) {
    return (unsigned)__cvta_generic_to_shared(p);
}
__device__ __forceinline__ void split2(float x, float y, unsigned& h, unsigned& l) {
    __nv_bfloat162 hh = __floats2bfloat162_rn(x, y);
    float rx = x - __low2float(hh);
    float ry = y - __high2float(hh);
    __nv_bfloat162 ll = __floats2bfloat162_rn(rx, ry);
    h = *reinterpret_cast<unsigned*>(&hh);
    l = *reinterpret_cast<unsigned*>(&ll);
}
__device__ __forceinline__ void split8(const float* v, uint4& h, uint4& l) {
    split2(v[0], v[1], h.x, l.x);
    split2(v[2], v[3], h.y, l.y);
    split2(v[4], v[5], h.z, l.z);
    split2(v[6], v[7], h.w, l.w);
}
__device__ __forceinline__ void mma16(float* c, const unsigned* a, const unsigned* b) {
    asm volatile("mma.sync.aligned.m16n8k16.row.col.f32.bf16.bf16.f32 "
        "{%0,%1,%2,%3},{%4,%5,%6,%7},{%8,%9},{%0,%1,%2,%3};"
        : "+f"(c[0]), "+f"(c[1]), "+f"(c[2]), "+f"(c[3])
        : "r"(a[0]), "r"(a[1]), "r"(a[2]), "r"(a[3]), "r"(b[0]), "r"(b[1]));
}
__device__ __forceinline__ void ldsm4(uint4& r, unsigned a) {
    asm volatile("ldmatrix.sync.aligned.m8n8.x4.shared.b16 {%0,%1,%2,%3},[%4];"
        : "=r"(r.x), "=r"(r.y), "=r"(r.z), "=r"(r.w) : "r"(a));
}
__device__ __forceinline__ void ldsm4t(uint4& r, unsigned a) {
    asm volatile("ldmatrix.sync.aligned.m8n8.x4.trans.shared.b16 {%0,%1,%2,%3},[%4];"
        : "=r"(r.x), "=r"(r.y), "=r"(r.z), "=r"(r.w) : "r"(a));
}
__device__ __forceinline__ void tile3(float* acc, const uint4& ah, const uint4& al,
                                      unsigned bh0, unsigned bh1, unsigned bl0, unsigned bl1) {
    unsigned A[4] = {ah.x, ah.y, ah.z, ah.w};
    unsigned L[4] = {al.x, al.y, al.z, al.w};
    unsigned BH[2] = {bh0, bh1}, BL[2] = {bl0, bl1};
    mma16(acc, A, BH);
    mma16(acc, L, BH);
    mma16(acc, A, BL);
}

// One BK=32 stage via ldmatrix. ATR=false: A from MK (no-trans); true: A from KN (.trans).
template<bool ATR>
__device__ __forceinline__ void mma_stage(unsigned fAh, unsigned fAl,
                                          unsigned fBh, unsigned fBl,
                                          float (*acc)[4]) {
    const int aMT = ATR ? 32 : 1280;
    const int aO  = ATR ? 4352 : 32;
#pragma unroll
    for (int o = 0; o < 2; ++o) {
        uint4 ah[4], al[4], bh[2], bl[2];
#pragma unroll
        for (int mt = 0; mt < 4; ++mt) {
            if (ATR) { ldsm4t(ah[mt], fAh + o * aO + mt * aMT); ldsm4t(al[mt], fAl + o * aO + mt * aMT); }
            else     { ldsm4 (ah[mt], fAh + o * aO + mt * aMT); ldsm4 (al[mt], fAl + o * aO + mt * aMT); }
        }
#pragma unroll
        for (int p = 0; p < 2; ++p) {
            ldsm4t(bh[p], fBh + o * 4352 + p * 32);
            ldsm4t(bl[p], fBl + o * 4352 + p * 32);
        }
#pragma unroll
        for (int mt = 0; mt < 4; ++mt)
#pragma unroll
            for (int p = 0; p < 2; ++p) {
                tile3(acc[mt * 4 + 2 * p],     ah[mt], al[mt], bh[p].x, bh[p].y, bl[p].x, bl[p].y);
                tile3(acc[mt * 4 + 2 * p + 1], ah[mt], al[mt], bh[p].z, bh[p].w, bl[p].z, bl[p].w);
            }
    }
}

// ---------------- generic projection GEMM core (double-buffered) --------
__device__ __forceinline__ void gemm_core(const float* __restrict__ A,
                                          const float* __restrict__ B,
                                          float* __restrict__ C,
                                          int N, int K, int m0, int n0, char* sm) {
    const unsigned smb = sptr(sm);
    const int tid = threadIdx.x, lane = tid & 31, w = tid >> 5;
    const int g = lane >> 2, t = lane & 3;
    const int mbase = (w & 1) * 64, nbase = (w >> 1) * 32;
    const int arow = tid >> 1, kseg = (tid & 1) * 16;
    const int krow = tid >> 3, nseg = (tid & 7) * 16;
    const bool bval = (n0 + nseg) < N;
    const unsigned offA = ((mbase + (lane & 15)) * MKS + (lane >> 4) * 8) * 2;
    const unsigned offB = ((((lane >> 3) & 1) * 8 + (lane & 7)) * KNS + nbase + ((lane >> 4) & 1) * 8) * 2;

    float acc[16][4];
#pragma unroll
    for (int i = 0; i < 16; ++i) acc[i][0] = acc[i][1] = acc[i][2] = acc[i][3] = 0.f;

    float4 ra[4], rb[4];
    auto loadRegs = [&](int k0) {
#pragma unroll
        for (int i = 0; i < 4; ++i) {
            ra[i] = *(const float4*)(A + (size_t)(m0 + arow) * K + k0 + kseg + 4 * i);
            rb[i] = bval ? *(const float4*)(B + (size_t)(k0 + krow) * N + n0 + nseg + 4 * i)
                         : make_float4(0.f, 0.f, 0.f, 0.f);
        }
    };
    auto storeStage = [&](int bsel) {
        bf16* Ah = (bf16*)(sm + bsel * GSTR);
        bf16* Al = (bf16*)(sm + bsel * GSTR + ABYT);
        bf16* Bh = (bf16*)(sm + bsel * GSTR + 2 * ABYT);
        bf16* Bl = (bf16*)(sm + bsel * GSTR + 2 * ABYT + BBYT);
        uint4 h4, l4;
        split8((const float*)&ra[0], h4, l4);
        *(uint4*)(Ah + arow * MKS + kseg) = h4;     *(uint4*)(Al + arow * MKS + kseg) = l4;
        split8((const float*)&ra[2], h4, l4);
        *(uint4*)(Ah + arow * MKS + kseg + 8) = h4; *(uint4*)(Al + arow * MKS + kseg + 8) = l4;
        split8((const float*)&rb[0], h4, l4);
        *(uint4*)(Bh + krow * KNS + nseg) = h4;     *(uint4*)(Bl + krow * KNS + nseg) = l4;
        split8((const float*)&rb[2], h4, l4);
        *(uint4*)(Bh + krow * KNS + nseg + 8) = h4; *(uint4*)(Bl + krow * KNS + nseg + 8) = l4;
    };

    const int NSt = K >> 5;
    loadRegs(0);
    storeStage(0);
    loadRegs(32);
    __syncthreads();
    for (int s = 0; s < NSt; ++s) {
        const unsigned sb = smb + (s & 1) * GSTR;
        mma_stage<false>(sb + offA, sb + ABYT + offA,
                         sb + 2 * ABYT + offB, sb + 2 * ABYT + BBYT + offB, acc);
        if (s + 1 < NSt) {
            storeStage((s + 1) & 1);
            if (s + 2 < NSt) loadRegs((s + 2) * 32);
        }
        __syncthreads();
    }
#pragma unroll
    for (int mt = 0; mt < 4; ++mt) {
        const int r0 = m0 + mbase + mt * 16 + g;
#pragma unroll
        for (int nt = 0; nt < 4; ++nt) {
            const int col = n0 + nbase + nt * 8 + t * 2;
            if (col < N) {
                const float* a4 = acc[mt * 4 + nt];
                *(float2*)(C + (size_t)r0 * N + col)       = make_float2(a4[0], a4[1]);
                *(float2*)(C + (size_t)(r0 + 8) * N + col) = make_float2(a4[2], a4[3]);
            }
        }
    }
}

// Combined Wv + Wq + Wk projections in one launch (tail smoothing).
__global__ __launch_bounds__(256) void proj_all(const float* __restrict__ x,
                                                const float* __restrict__ Wq,
                                                const float* __restrict__ Wk,
                                                const float* __restrict__ Wv) {
    extern __shared__ char sm[];
    const int bx = blockIdx.x, m0 = blockIdx.y * 128;
    if (bx < 12) {
        gemm_core(x, Wv, (float*)g_v, DMODEL, DMODEL, m0, bx * 128, sm);
    } else if (bx < 14) {
        gemm_core(x, Wq, (float*)g_q, QKDIM, DMODEL, m0, (bx - 12) * 128, sm);
    } else {
        gemm_core(x, Wk, (float*)g_k, QKDIM, DMODEL, m0, (bx - 14) * 128, sm);
    }
}

__global__ __launch_bounds__(256) void proj_kernel(const float* __restrict__ A,
                                                   const float* __restrict__ B,
                                                   float* __restrict__ C, int N, int K) {
    extern __shared__ char sm[];
    gemm_core(A, B, C, N, K, blockIdx.y * 128, blockIdx.x * 128, sm);
}

// ---------------- LayerNorm over 192 dims, in place ----------------
__global__ __launch_bounds__(256) void ln_kernel(const float* __restrict__ gq,
                                                 const float* __restrict__ bq,
                                                 const float* __restrict__ gk,
                                                 const float* __restrict__ bk) {
    const int warp = (blockIdx.x * blockDim.x + threadIdx.x) >> 5;
    const int lane = threadIdx.x & 31;
    if (warp >= 2 * NTOK) return;
    const bool isq = warp < NTOK;
    float* p = isq ? (g_q + (size_t)warp * QKDIM) : (g_k + (size_t)(warp - NTOK) * QKDIM);
    const float* gg = isq ? gq : gk;
    const float* bb = isq ? bq : bk;
    float x[6]; float s = 0.f, s2 = 0.f;
#pragma unroll
    for (int i = 0; i < 6; ++i) { x[i] = p[lane + 32 * i]; s += x[i]; s2 = fmaf(x[i], x[i], s2); }
#pragma unroll
    for (int o = 16; o > 0; o >>= 1) {
        s += __shfl_xor_sync(0xffffffffu, s, o);
        s2 += __shfl_xor_sync(0xffffffffu, s2, o);
    }
    const float mu = s * (1.f / QKDIM);
    const float var = s2 * (1.f / QKDIM) - mu * mu;
    const float r = rsqrtf(var + LN_EPS);
#pragma unroll
    for (int i = 0; i < 6; ++i) {
        const int c = lane + 32 * i;
        p[c] = (x[i] - mu) * r * gg[c] + bb[c];
    }
}

// ---------------- per-chunk state: S_c = k2_c^T v_c, z_c = sum k2_c ------
__global__ __launch_bounds__(256) void kvstate_db() {
    extern __shared__ char sm[];
    const unsigned smb = sptr(sm);
    float* ksm = (float*)(sm + 2 * KSTR);     // 128*17 fp32; reused as zred
    const int gx = blockIdx.x;
    const int dhalf = gx & 1, rest = gx >> 1;
    const int ch = rest & (NC - 1), bh = rest / NC;
    const int b = bh / HH, h = bh % HH;
    const int d0 = dhalf * 128;
    const int tid = threadIdx.x, lane = tid & 31, w = tid >> 5;
    const int g = lane >> 2, t = lane & 3;
    const int mbase = (w & 1) * 64, nbase = (w >> 1) * 32;
    const int pc = tid >> 4, eg = (tid & 15) * 8;

    const float* kb = g_k + (size_t)(b * LLEN + ch * CH) * QKDIM + h * FDIM;
    const float* vb = g_v + (size_t)(b * LLEN + ch * CH) * DMODEL + h * DVDIM;

#pragma unroll
    for (int u = 0; u < 2; ++u) {
        const int lin = tid * 2 + u;
        const int r = lin >> 2, c4 = (lin & 3) * 4;
        float4 kv = *(const float4*)(kb + (size_t)r * QKDIM + c4);
        ksm[r * 17 + c4 + 0] = kv.x; ksm[r * 17 + c4 + 1] = kv.y;
        ksm[r * 17 + c4 + 2] = kv.z; ksm[r * 17 + c4 + 3] = kv.w;
    }

    const int iA = (d0 + eg) >> 4, jb = eg & 15;
    const unsigned offA = ((((lane >> 4) & 1) * 8 + (lane & 7)) * KNS + mbase + ((lane >> 3) & 1) * 8) * 2;
    const unsigned offB = ((((lane >> 3) & 1) * 8 + (lane & 7)) * KNS + nbase + ((lane >> 4) & 1) * 8) * 2;

    float acc[16][4];
#pragma unroll
    for (int i = 0; i < 16; ++i) acc[i][0] = acc[i][1] = acc[i][2] = acc[i][3] = 0.f;
    float zacc[8];
#pragma unroll
    for (int e = 0; e < 8; ++e) zacc[e] = 0.f;

    float vA[8], vB[8];
    auto loadV = [&](int c0) {
        const float* r0p = vb + (size_t)(c0 + 2 * pc) * DMODEL + eg;
        const float* r1p = vb + (size_t)(c0 + 2 * pc + 1) * DMODEL + eg;
        *(float4*)&vA[0] = *(const float4*)r0p; *(float4*)&vA[4] = *(const float4*)(r0p + 4);
        *(float4*)&vB[0] = *(const float4*)r1p; *(float4*)&vB[4] = *(const float4*)(r1p + 4);
    };
    auto stage = [&](int bsel, int c0) {
        bf16* Ah = (bf16*)(sm + bsel * KSTR);
        bf16* Al = (bf16*)(sm + bsel * KSTR + BBYT);
        bf16* Bh = (bf16*)(sm + bsel * KSTR + 2 * BBYT);
        bf16* Bl = (bf16*)(sm + bsel * KSTR + 3 * BBYT);
        const int ca = c0 + 2 * pc, cb2 = ca + 1;
        float pa[8], pb[8];
        const float kia = ksm[ca * 17 + iA] * 0.25f;
        const float kib = ksm[cb2 * 17 + iA] * 0.25f;
#pragma unroll
        for (int e = 0; e < 8; ++e) {
            pa[e] = kia * ksm[ca * 17 + jb + e];
            pb[e] = kib * ksm[cb2 * 17 + jb + e];
            zacc[e] += pa[e] + pb[e];
        }
        uint4 h4, l4;
        split8(pa, h4, l4);
        *(uint4*)(Ah + (2 * pc) * KNS + eg) = h4;     *(uint4*)(Al + (2 * pc) * KNS + eg) = l4;
        split8(pb, h4, l4);
        *(uint4*)(Ah + (2 * pc + 1) * KNS + eg) = h4; *(uint4*)(Al + (2 * pc + 1) * KNS + eg) = l4;
        split8(vA, h4, l4);
        *(uint4*)(Bh + (2 * pc) * KNS + eg) = h4;     *(uint4*)(Bl + (2 * pc) * KNS + eg) = l4;
        split8(vB, h4, l4);
        *(uint4*)(Bh + (2 * pc + 1) * KNS + eg) = h4; *(uint4*)(Bl + (2 * pc + 1) * KNS + eg) = l4;
    };

    loadV(0);
    __syncthreads();            // ksm visible
    stage(0, 0);
    loadV(32);
    __syncthreads();
    for (int s = 0; s < 4; ++s) {
        const unsigned sb = smb + (s & 1) * KSTR;
        mma_stage<true>(sb + offA, sb + BBYT + offA,
                        sb + 2 * BBYT + offB, sb + 3 * BBYT + offB, acc);
        if (s + 1 < 4) {
            stage((s + 1) & 1, (s + 1) * 32);
            if (s + 2 < 4) loadV((s + 2) * 32);
        }
        __syncthreads();
    }

    float* Sout = g_S + (((size_t)bh * NC + ch) * D2 + d0) * DVDIM;
#pragma unroll
    for (int mt = 0; mt < 4; ++mt) {
        const int r0 = mbase + mt * 16 + g;
#pragma unroll
        for (int nt = 0; nt < 4; ++nt) {
            const int col = nbase + nt * 8 + t * 2;
            const float* a4 = acc[mt * 4 + nt];
            *(float2*)(Sout + (size_t)r0 * DVDIM + col)       = make_float2(a4[0], a4[1]);
            *(float2*)(Sout + (size_t)(r0 + 8) * DVDIM + col) = make_float2(a4[2], a4[3]);
        }
    }
    // z reduction: reuse ksm region as zred[16][128]
#pragma unroll
    for (int e = 0; e < 8; ++e) ksm[pc * 128 + eg + e] = zacc[e];
    __syncthreads();
    if (tid < 128) {
        float z = 0.f;
#pragma unroll
        for (int p = 0; p < 16; ++p) z += ksm[p * 128 + tid];
        g_z[((size_t)bh * NC + ch) * D2 + d0 + tid] = z;
    }
}

// ---------------- exclusive prefix over chunks (batched MLP-16 loads) ----
__global__ __launch_bounds__(256) void prefix_kernel() {
    const int NS4 = BB * HH * D2 * DVDIM / 4;   // 196608 float4 lanes
    const int NZ4 = BB * HH * D2 / 4;           // 1536 float4 lanes
    const int idx = blockIdx.x * blockDim.x + threadIdx.x;
    if (idx < NS4) {
        const int per = D2 * DVDIM / 4;
        const int bh = idx / per;
        const int rem = idx % per;
        float4* base = (float4*)(g_S + (size_t)bh * NC * D2 * DVDIM) + rem;
        const int stride = D2 * DVDIM / 4;
        float4 v[NC];
#pragma unroll
        for (int c = 0; c < NC; ++c) v[c] = base[(size_t)c * stride];
        float rx = 0.f, ry = 0.f, rz = 0.f, rw = 0.f;
#pragma unroll
        for (int c = 0; c < NC; ++c) {
            const float4 t = v[c];
            v[c] = make_float4(rx, ry, rz, rw);
            rx += t.x; ry += t.y; rz += t.z; rw += t.w;
        }
#pragma unroll
        for (int c = 0; c < NC; ++c) base[(size_t)c * stride] = v[c];
    } else if (idx < NS4 + NZ4) {
        const int j = idx - NS4;
        const int per = D2 / 4;
        const int bh = j / per;
        const int rem = j % per;
        float4* base = (float4*)(g_z + (size_t)bh * NC * D2) + rem;
        const int stride = D2 / 4;
        float4 v[NC];
#pragma unroll
        for (int c = 0; c < NC; ++c) v[c] = base[(size_t)c * stride];
        float rx = 0.f, ry = 0.f, rz = 0.f, rw = 0.f;
#pragma unroll
        for (int c = 0; c < NC; ++c) {
            const float4 t = v[c];
            v[c] = make_float4(rx, ry, rz, rw);
            rx += t.x; ry += t.y; rz += t.z; rw += t.w;
        }
#pragma unroll
        for (int c = 0; c < NC; ++c) base[(size_t)c * stride] = v[c];
    }
}

// ---------------- fused attention: A+den prologue, then (q2 S + A v)/den --
__global__ __launch_bounds__(256) void attn_fused() {
    extern __shared__ char sm[];
    const unsigned smb = sptr(sm);
    float* qsm  = (float*)(sm + AQSM);          // persistent 128*17 fp32
    float* dens = (float*)(sm + ADEN);          // persistent 128 fp32
    // prologue-only aliases (inside double-buffer region, dead after first stage)
    float* ksm  = (float*)(sm);                 // 128*17 fp32 = 8704
    float* Zs   = (float*)(sm + 8704);          // 256 fp32
    float* rsum = (float*)(sm + 9728);          // 256 fp32

    const int gx = blockIdx.x;
    const int ch = gx & (NC - 1), bh = gx / NC;
    const int b = bh / HH, h = bh % HH;
    const int tid = threadIdx.x, lane = tid & 31, w = tid >> 5;
    const int g = lane >> 2, t = lane & 3;
    const int mbase = (w & 1) * 64, nbase = (w >> 1) * 32;
    const int arow = tid >> 1, kseg = (tid & 1) * 16;
    const int pkr = tid >> 4, bn = (tid & 15) * 8;

    const float* qb = g_q + (size_t)(b * LLEN + ch * CH) * QKDIM + h * FDIM;
    const float* kb = g_k + (size_t)(b * LLEN + ch * CH) * QKDIM + h * FDIM;
    const float* Sb = g_S + ((size_t)bh * NC + ch) * D2 * DVDIM;
    const float* vb = g_v + (size_t)(b * LLEN + ch * CH) * DMODEL + h * DVDIM;

    const unsigned offA = ((mbase + (lane & 15)) * MKS + (lane >> 4) * 8) * 2;
    const unsigned offB = ((((lane >> 3) & 1) * 8 + (lane & 7)) * KNS + nbase + ((lane >> 4) & 1) * 8) * 2;

    // ---- prologue: load q,k,Z; compute A (into Areg, bf16 hi/lo MK tiles) + den
#pragma unroll
    for (int u = 0; u < 2; ++u) {
        const int lin = tid * 2 + u;
        const int r = lin >> 2, c4 = (lin & 3) * 4;
        float4 qv = *(const float4*)(qb + (size_t)r * QKDIM + c4);
        qsm[r * 17 + c4 + 0] = qv.x; qsm[r * 17 + c4 + 1] = qv.y;
        qsm[r * 17 + c4 + 2] = qv.z; qsm[r * 17 + c4 + 3] = qv.w;
        float4 kv = *(const float4*)(kb + (size_t)r * QKDIM + c4);
        ksm[r * 17 + c4 + 0] = kv.x; ksm[r * 17 + c4 + 1] = kv.y;
        ksm[r * 17 + c4 + 2] = kv.z; ksm[r * 17 + c4 + 3] = kv.w;
    }
    Zs[tid] = g_z[((size_t)bh * NC + ch) * D2 + tid];
    __syncthreads();
    {
        const int r = tid >> 1, cb = (tid & 1) * 64;
        float qr[16];
#pragma unroll
        for (int i = 0; i < 16; ++i) qr[i] = qsm[r * 17 + i];
        float rs = 0.f;
        for (int cc = 0; cc < 64; cc += 4) {
            float ap[4];
#pragma unroll
            for (int e = 0; e < 4; ++e) {
                const int c = cb + cc + e;
                float sd = 0.f;
#pragma unroll
                for (int i = 0; i < 16; ++i) sd = fmaf(qr[i], ksm[c * 17 + i], sd);
                const float a = (c <= r) ? sd * sd * 0.0625f : 0.f;
                ap[e] = a; rs += a;
            }
            const int c0 = cb + cc;
            const int tile = c0 >> 5, kk = c0 & 31;
            bf16* Ath = (bf16*)(sm + AREG + tile * 2 * ABYT);
            bf16* Atl = (bf16*)(sm + AREG + tile * 2 * ABYT + ABYT);
            unsigned h0, l0, h1, l1;
            split2(ap[0], ap[1], h0, l0);
            split2(ap[2], ap[3], h1, l1);
            *(uint2*)(Ath + r * MKS + kk) = make_uint2(h0, h1);
            *(uint2*)(Atl + r * MKS + kk) = make_uint2(l0, l1);
        }
        rsum[tid] = rs;
    }
    __syncthreads();
    if (tid < 128) {
        float den = 0.f;
#pragma unroll
        for (int i = 0; i < 16; ++i) {
            float y = 0.f;
#pragma unroll
            for (int j = 0; j < 16; ++j) y = fmaf(Zs[i * 16 + j], qsm[tid * 17 + j], y);
            den = fmaf(qsm[tid * 17 + i], y, den);
        }
        dens[tid] = den * 0.25f + rsum[2 * tid] + rsum[2 * tid + 1];
    }

    // ---- pipeline: 8 stages q2@S (A generated), 4 stages A(from Areg)@v
    float acc[16][4];
#pragma unroll
    for (int i = 0; i < 16; ++i) acc[i][0] = acc[i][1] = acc[i][2] = acc[i][3] = 0.f;

    float bA[8], bB[8];
    auto loadB = [&](int s) {
        const float* r0p;
        const float* r1p;
        if (s < 8) {
            r0p = Sb + (size_t)(s * 32 + 2 * pkr) * DVDIM + bn;
            r1p = Sb + (size_t)(s * 32 + 2 * pkr + 1) * DVDIM + bn;
        } else {
            r0p = vb + (size_t)((s - 8) * 32 + 2 * pkr) * DMODEL + bn;
            r1p = vb + (size_t)((s - 8) * 32 + 2 * pkr + 1) * DMODEL + bn;
        }
        *(float4*)&bA[0] = *(const float4*)r0p; *(float4*)&bA[4] = *(const float4*)(r0p + 4);
        *(float4*)&bB[0] = *(const float4*)r1p; *(float4*)&bB[4] = *(const float4*)(r1p + 4);
    };
    auto stage = [&](int bsel, int s) {
        bf16* Bh = (bf16*)(sm + bsel * GSTR + 2 * ABYT);
        bf16* Bl = (bf16*)(sm + bsel * GSTR + 2 * ABYT + BBYT);
        uint4 h4, l4;
        if (s < 8) {
            bf16* Ah = (bf16*)(sm + bsel * GSTR);
            bf16* Al = (bf16*)(sm + bsel * GSTR + ABYT);
            const int db = s * 32 + kseg;
            const float qi = qsm[arow * 17 + (db >> 4)] * 0.25f;
            float p[16];
#pragma unroll
            for (int j = 0; j < 16; ++j) p[j] = qi * qsm[arow * 17 + j];
            split8(p, h4, l4);
            *(uint4*)(Ah + arow * MKS + kseg) = h4;     *(uint4*)(Al + arow * MKS + kseg) = l4;
            split8(p + 8, h4, l4);
            *(uint4*)(Ah + arow * MKS + kseg + 8) = h4; *(uint4*)(Al + arow * MKS + kseg + 8) = l4;
        }
        split8(bA, h4, l4);
        *(uint4*)(Bh + (2 * pkr) * KNS + bn) = h4;     *(uint4*)(Bl + (2 * pkr) * KNS + bn) = l4;
        split8(bB, h4, l4);
        *(uint4*)(Bh + (2 * pkr + 1) * KNS + bn) = h4; *(uint4*)(Bl + (2 * pkr + 1) * KNS + bn) = l4;
    };

    loadB(0);
    __syncthreads();            // prologue reads done; buffers reusable
    stage(0, 0);
    loadB(1);
    __syncthreads();
    for (int s = 0; s < 12; ++s) {
        const unsigned sb = smb + (s & 1) * GSTR;
        unsigned fAh, fAl;
        if (s < 8) { fAh = sb + offA; fAl = sb + ABYT + offA; }
        else {
            fAh = smb + AREG + (s - 8) * 2 * ABYT + offA;
            fAl = fAh + ABYT;
        }
        mma_stage<false>(fAh, fAl,
                         sb + 2 * ABYT + offB, sb + 2 * ABYT + BBYT + offB, acc);
        if (s + 1 < 12) {
            stage((s + 1) & 1, s + 1);
            if (s + 2 < 12) loadB(s + 2);
        }
        __syncthreads();
    }

    float* ob = g_oh + (size_t)(b * LLEN + ch * CH) * DMODEL + h * DVDIM;
#pragma unroll
    for (int mt = 0; mt < 4; ++mt) {
        const int r0 = mbase + mt * 16 + g;
        const float inv0 = 1.f / (dens[r0] + EPS);
        const float inv1 = 1.f / (dens[r0 + 8] + EPS);
#pragma unroll
        for (int nt = 0; nt < 4; ++nt) {
            const int col = nbase + nt * 8 + t * 2;
            const float* a4 = acc[mt * 4 + nt];
            *(float2*)(ob + (size_t)r0 * DMODEL + col)       = make_float2(a4[0] * inv0, a4[1] * inv0);
            *(float2*)(ob + (size_t)(r0 + 8) * DMODEL + col) = make_float2(a4[2] * inv1, a4[3] * inv1);
        }
    }
}

// ---------------- host pipeline ----------------
extern "C" void kernel_launch(void* const* d_in, const int* in_sizes, int n_in,
                              void* d_out, int out_size) {
    (void)in_sizes; (void)n_in; (void)out_size;
    const float* x   = (const float*)d_in[0];
    const float* Wq  = (const float*)d_in[1];
    const float* Wk  = (const float*)d_in[2];
    const float* Wv  = (const float*)d_in[3];
    const float* Wo  = (const float*)d_in[4];
    const float* lqg = (const float*)d_in[5];
    const float* lqb = (const float*)d_in[6];
    const float* lkg = (const float*)d_in[7];
    const float* lkb = (const float*)d_in[8];
    float* out = (float*)d_out;

    const int GEMM_SM = 2 * GSTR;               // 75776
    const int KV_SM   = 2 * KSTR + 8704;        // 78336
    cudaFuncSetAttribute(proj_all,    cudaFuncAttributeMaxDynamicSharedMemorySize, GEMM_SM);
    cudaFuncSetAttribute(proj_kernel, cudaFuncAttributeMaxDynamicSharedMemorySize, GEMM_SM);
    cudaFuncSetAttribute(kvstate_db,  cudaFuncAttributeMaxDynamicSharedMemorySize, KV_SM);
    cudaFuncSetAttribute(attn_fused,  cudaFuncAttributeMaxDynamicSharedMemorySize, ATTN_SM);

    float *ohp;
    cudaGetSymbolAddress((void**)&ohp, g_oh);

    proj_all<<<dim3(16, 32), 256, GEMM_SM>>>(x, Wq, Wk, Wv);
    ln_kernel<<<(2 * NTOK) / 8, 256>>>(lqg, lqb, lkg, lkb);
    kvstate_db<<<BB * HH * NC * 2, 256, KV_SM>>>();
    {
        const int total4 = BB * HH * D2 * DVDIM / 4 + BB * HH * D2 / 4;
        prefix_kernel<<<(total4 + 255) / 256, 256>>>();
    }
    attn_fused<<<BB * HH * NC, 256, ATTN_SM>>>();
    proj_kernel<<<dim3(12, 32), 256, GEMM_SM>>>(ohp, Wo, out, DMODEL, DMODEL);
}